// round 2
// baseline (speedup 1.0000x reference)
#include <cuda_runtime.h>

// Problem constants
#define NB   64
#define NT   1025      // tokens = 1024 patches + cls
#define ND   256       // token dim
#define NH   1024      // FFN hidden
#define NCLS 1000

// ---------------- static scratch (no allocations allowed) ----------------
__device__ float g_t  [64LL*1025*256];
__device__ float g_h  [64LL*1025*256];
__device__ float g_U  [64LL*1025*256];
__device__ float g_V  [64LL*1025*256];
__device__ float g_hid[64LL*1025*1024];
__device__ float g_Cd[256*256];
__device__ float g_Sd[256*256];
__device__ float g_Cn[1025LL*1025];
__device__ float g_Sn[1025LL*1025];
__device__ float g_wT[768*256];
__device__ float g_pooled[64*256];

// ---------------- small helpers ----------------
__device__ __forceinline__ float warp_sum(float v) {
#pragma unroll
    for (int o = 16; o > 0; o >>= 1) v += __shfl_xor_sync(0xffffffffu, v, o);
    return v;
}
__device__ __forceinline__ float warp_max(float v) {
#pragma unroll
    for (int o = 16; o > 0; o >>= 1) v = fmaxf(v, __shfl_xor_sync(0xffffffffu, v, o));
    return v;
}
// blockDim.x == 256 assumed
__device__ float block_sum(float v, float* sbuf) {
    int tid = threadIdx.x;
    float w = warp_sum(v);
    if ((tid & 31) == 0) sbuf[tid >> 5] = w;
    __syncthreads();
    float r = (tid < 8) ? sbuf[tid] : 0.f;
    if (tid < 32) { r = warp_sum(r); if (tid == 0) sbuf[0] = r; }
    __syncthreads();
    float res = sbuf[0];
    __syncthreads();
    return res;
}
__device__ float block_max(float v, float* sbuf) {
    int tid = threadIdx.x;
    float w = warp_max(v);
    if ((tid & 31) == 0) sbuf[tid >> 5] = w;
    __syncthreads();
    float r = (tid < 8) ? sbuf[tid] : -3.4e38f;
    if (tid < 32) { r = warp_max(r); if (tid == 0) sbuf[0] = r; }
    __syncthreads();
    float res = sbuf[0];
    __syncthreads();
    return res;
}

// ---------------- DFT matrix fill (exact integer phase reduction) ----------------
__global__ void fill_dft_d() {
    int i = blockIdx.x, j = threadIdx.x;
    int r = (i * j) % ND;
    float s, c;
    sincospif(2.0f * (float)r / (float)ND, &s, &c);
    g_Cd[i * ND + j] = c;
    g_Sd[i * ND + j] = s;
}
__global__ void fill_dft_n() {
    int i = blockIdx.x;
    for (int j = threadIdx.x; j < NT; j += 256) {
        int r = (int)(((long long)i * (long long)j) % NT);
        float s, c;
        sincospif(2.0f * (float)r / (float)NT, &s, &c);
        g_Cn[(long long)i * NT + j] = c;
        g_Sn[(long long)i * NT + j] = s;
    }
}

// ---------------- weight transpose: conv_w (256,768) -> wT (768,256) ----------------
__global__ void transpose_w(const float* __restrict__ w) {
    int k = blockIdx.x;      // 0..767
    int d = threadIdx.x;     // 0..255
    g_wT[k * ND + d] = w[(long long)d * 768 + k];
}

// ---------------- patch embed: tok[b,p,d] = sum_k patch[k]*w[d,k] ----------------
// grid (128, 64), block 256. 8 patches per block.
__global__ void patch_embed(const float* __restrict__ x) {
    __shared__ float sp[8][768];
    int b  = blockIdx.y;
    int p0 = blockIdx.x * 8;
    int tid = threadIdx.x;
    for (int i = tid; i < 8 * 768; i += 256) {
        int pi = i / 768, k = i % 768;
        int p = p0 + pi;
        int gh = p >> 5, gw = p & 31;
        int c = k >> 8, rem = k & 255, r = rem >> 4, q = rem & 15;
        sp[pi][k] = x[(((long long)b * 3 + c) * 512 + gh * 16 + r) * 512 + gw * 16 + q];
    }
    __syncthreads();
    float acc[8] = {0.f,0.f,0.f,0.f,0.f,0.f,0.f,0.f};
    int d = tid;
#pragma unroll 4
    for (int k = 0; k < 768; k++) {
        float w = g_wT[k * ND + d];
#pragma unroll
        for (int pi = 0; pi < 8; pi++) acc[pi] = fmaf(sp[pi][k], w, acc[pi]);
    }
#pragma unroll
    for (int pi = 0; pi < 8; pi++) {
        int p = p0 + pi;
        g_t[((long long)b * NT + 1 + p) * ND + d] = acc[pi];
    }
}

// ---------------- assemble: cls token, pos emb, conv bias ----------------
// grid (1025, 64), block 256
__global__ void assemble(const float* __restrict__ conv_b,
                         const float* __restrict__ pos,
                         const float* __restrict__ cls) {
    int n = blockIdx.x, b = blockIdx.y, d = threadIdx.x;
    long long off = ((long long)b * NT + n) * ND + d;
    if (n == 0) g_t[off] = cls[d] + pos[d];
    else        g_t[off] += conv_b[d] + pos[(long long)n * ND + d];
}

// ---------------- layernorm over last dim (256), one row per block ----------------
__global__ void ln_kernel(const float* __restrict__ in, float* __restrict__ out,
                          const float* __restrict__ gam, const float* __restrict__ bet) {
    __shared__ float sbuf[32];
    long long row = blockIdx.x;
    int tid = threadIdx.x;
    float v = in[row * ND + tid];
    float mean = block_sum(v, sbuf) * (1.f / 256.f);
    float d = v - mean;
    float var = block_sum(d * d, sbuf) * (1.f / 256.f);
    out[row * ND + tid] = d * rsqrtf(var + 1e-5f) * gam[tid] + bet[tid];
}

// ---------------- fused dual GEMM: U = h*Cd, V = h*Sd ----------------
// M=65600, K=256, N=256 (all tile-exact). grid (4, 1025), block 256.
__global__ void dft_gemm() {
    __shared__ float As[16][68], B1s[16][68], B2s[16][68];
    int tid = threadIdx.x;
    int tx = tid & 15, ty = tid >> 4;
    int m0 = blockIdx.y << 6, n0 = blockIdx.x << 6;
    int arow = tid >> 2, acol = (tid & 3) << 2;
    int brow = tid >> 4, bcol = (tid & 15) << 2;
    float acc1[4][4] = {}, acc2[4][4] = {};
    for (int k0 = 0; k0 < ND; k0 += 16) {
        float4 av = *(const float4*)&g_h[(long long)(m0 + arow) * ND + k0 + acol];
        As[acol + 0][arow] = av.x; As[acol + 1][arow] = av.y;
        As[acol + 2][arow] = av.z; As[acol + 3][arow] = av.w;
        int kb = k0 + brow;
        *(float4*)&B1s[brow][bcol] = *(const float4*)&g_Cd[kb * ND + n0 + bcol];
        *(float4*)&B2s[brow][bcol] = *(const float4*)&g_Sd[kb * ND + n0 + bcol];
        __syncthreads();
#pragma unroll
        for (int k = 0; k < 16; k++) {
            float4 a  = *(const float4*)&As[k][ty << 2];
            float4 b1 = *(const float4*)&B1s[k][tx << 2];
            float4 b2 = *(const float4*)&B2s[k][tx << 2];
            float ar[4] = {a.x, a.y, a.z, a.w};
            float c1[4] = {b1.x, b1.y, b1.z, b1.w};
            float c2[4] = {b2.x, b2.y, b2.z, b2.w};
#pragma unroll
            for (int i = 0; i < 4; i++)
#pragma unroll
                for (int j = 0; j < 4; j++) {
                    acc1[i][j] = fmaf(ar[i], c1[j], acc1[i][j]);
                    acc2[i][j] = fmaf(ar[i], c2[j], acc2[i][j]);
                }
        }
        __syncthreads();
    }
#pragma unroll
    for (int i = 0; i < 4; i++) {
        long long row = m0 + (ty << 2) + i;
#pragma unroll
        for (int j = 0; j < 4; j++) {
            long long off = row * ND + n0 + (tx << 2) + j;
            g_U[off] = acc1[i][j];
            g_V[off] = acc2[i][j];
        }
    }
}

// ---------------- fused mixing GEMM: t += Cn*U - Sn*V (per batch) ----------------
// grid (4, 17, 64), block 256. M=K=1025 (guarded), N=256.
__global__ void mix_gemm() {
    __shared__ float A1s[16][68], A2s[16][68], B1s[16][68], B2s[16][68];
    int tid = threadIdx.x;
    int tx = tid & 15, ty = tid >> 4;
    int m0 = blockIdx.y << 6, n0 = blockIdx.x << 6;
    long long base = (long long)blockIdx.z * NT * ND;
    int arow = tid >> 2, acol = (tid & 3) << 2;
    int brow = tid >> 4, bcol = (tid & 15) << 2;
    float acc[4][4] = {};
    int m = m0 + arow;
    for (int k0 = 0; k0 < NT; k0 += 16) {
#pragma unroll
        for (int tt = 0; tt < 4; tt++) {
            int k = k0 + acol + tt;
            bool ok = (m < NT) && (k < NT);
            long long ai = (long long)m * NT + k;
            A1s[acol + tt][arow] = ok ? g_Cn[ai] : 0.f;
            A2s[acol + tt][arow] = ok ? g_Sn[ai] : 0.f;
        }
        int kb = k0 + brow;
        float4 b1 = make_float4(0.f, 0.f, 0.f, 0.f), b2 = b1;
        if (kb < NT) {
            long long bi = base + (long long)kb * ND + n0 + bcol;
            b1 = *(const float4*)&g_U[bi];
            b2 = *(const float4*)&g_V[bi];
        }
        *(float4*)&B1s[brow][bcol] = b1;
        *(float4*)&B2s[brow][bcol] = b2;
        __syncthreads();
#pragma unroll
        for (int k = 0; k < 16; k++) {
            float4 a1 = *(const float4*)&A1s[k][ty << 2];
            float4 a2 = *(const float4*)&A2s[k][ty << 2];
            float4 v1 = *(const float4*)&B1s[k][tx << 2];
            float4 v2 = *(const float4*)&B2s[k][tx << 2];
            float p[4] = {a1.x, a1.y, a1.z, a1.w};
            float q[4] = {a2.x, a2.y, a2.z, a2.w};
            float r[4] = {v1.x, v1.y, v1.z, v1.w};
            float s[4] = {v2.x, v2.y, v2.z, v2.w};
#pragma unroll
            for (int i = 0; i < 4; i++)
#pragma unroll
                for (int j = 0; j < 4; j++) {
                    acc[i][j] = fmaf(p[i], r[j], acc[i][j]);
                    acc[i][j] = fmaf(-q[i], s[j], acc[i][j]);
                }
        }
        __syncthreads();
    }
#pragma unroll
    for (int i = 0; i < 4; i++) {
        int mm = m0 + (ty << 2) + i;
        if (mm < NT) {
#pragma unroll
            for (int j = 0; j < 4; j++) {
                long long ci = base + (long long)mm * ND + n0 + (tx << 2) + j;
                g_t[ci] += acc[i][j];
            }
        }
    }
}

// ---------------- generic tiled SGEMM (exact tiles: M%64==0, N%64==0, K%16==0) ----------------
// BETA: accumulate into C; BIAS: add bias[n]; ACT: leaky relu(0.01)
template<int BETA, int BIAS, int ACT>
__global__ void sgemm_kernel(const float* __restrict__ A, const float* __restrict__ B,
                             float* __restrict__ C, const float* __restrict__ bias,
                             int M, int N, int K) {
    __shared__ float As[16][68], Bs[16][68];
    int tid = threadIdx.x;
    int tx = tid & 15, ty = tid >> 4;
    int m0 = blockIdx.y << 6, n0 = blockIdx.x << 6;
    int arow = tid >> 2, acol = (tid & 3) << 2;
    int brow = tid >> 4, bcol = (tid & 15) << 2;
    float acc[4][4] = {};
    const float* Ap = A + (long long)(m0 + arow) * K + acol;
    const float* Bp = B + (long long)brow * N + n0 + bcol;
    for (int k0 = 0; k0 < K; k0 += 16) {
        float4 av = *(const float4*)(Ap + k0);
        As[acol + 0][arow] = av.x; As[acol + 1][arow] = av.y;
        As[acol + 2][arow] = av.z; As[acol + 3][arow] = av.w;
        *(float4*)&Bs[brow][bcol] = *(const float4*)(Bp + (long long)k0 * N);
        __syncthreads();
#pragma unroll
        for (int k = 0; k < 16; k++) {
            float4 a = *(const float4*)&As[k][ty << 2];
            float4 b = *(const float4*)&Bs[k][tx << 2];
            float ar[4] = {a.x, a.y, a.z, a.w};
            float br[4] = {b.x, b.y, b.z, b.w};
#pragma unroll
            for (int i = 0; i < 4; i++)
#pragma unroll
                for (int j = 0; j < 4; j++)
                    acc[i][j] = fmaf(ar[i], br[j], acc[i][j]);
        }
        __syncthreads();
    }
#pragma unroll
    for (int i = 0; i < 4; i++) {
        long long row = m0 + (ty << 2) + i;
#pragma unroll
        for (int j = 0; j < 4; j++) {
            int n = n0 + (tx << 2) + j;
            float v = acc[i][j];
            if (BIAS) v += bias[n];
            if (ACT)  v = v > 0.f ? v : 0.01f * v;
            float* cp = &C[row * N + n];
            if (BETA) v += *cp;
            *cp = v;
        }
    }
}

// ---------------- mean pool over tokens ----------------
__global__ void pool_kernel() {
    int b = blockIdx.x, d = threadIdx.x;
    const float* p = g_t + (long long)b * NT * ND + d;
    float s = 0.f;
#pragma unroll 8
    for (int n = 0; n < NT; n++) s += p[(long long)n * ND];
    g_pooled[b * ND + d] = s * (1.f / 1025.f);
}

// ---------------- head: LN(pooled) @ head_w + head_b -> softmax ----------------
__global__ void head_kernel(const float* __restrict__ hw, const float* __restrict__ hb,
                            const float* __restrict__ gs, const float* __restrict__ gb,
                            float* __restrict__ out) {
    __shared__ float sbuf[32];
    __shared__ float lnp[256];
    int b = blockIdx.x, tid = threadIdx.x;
    float v = g_pooled[b * ND + tid];
    float mean = block_sum(v, sbuf) * (1.f / 256.f);
    float d = v - mean;
    float var = block_sum(d * d, sbuf) * (1.f / 256.f);
    lnp[tid] = d * rsqrtf(var + 1e-5f) * gs[tid] + gb[tid];
    __syncthreads();
    float lg[4];
#pragma unroll
    for (int j = 0; j < 4; j++) {
        int n = tid + j * 256;
        float s = -3.4e38f;
        if (n < NCLS) {
            s = hb[n];
            for (int k = 0; k < ND; k++) s = fmaf(lnp[k], hw[k * NCLS + n], s);
        }
        lg[j] = s;
    }
    float lmax = fmaxf(fmaxf(lg[0], lg[1]), fmaxf(lg[2], lg[3]));
    float mx = block_max(lmax, sbuf);
    float es = 0.f;
#pragma unroll
    for (int j = 0; j < 4; j++) {
        int n = tid + j * 256;
        if (n < NCLS) { lg[j] = expf(lg[j] - mx); es += lg[j]; }
    }
    float tot = block_sum(es, sbuf);
    float inv = 1.f / tot;
#pragma unroll
    for (int j = 0; j < 4; j++) {
        int n = tid + j * 256;
        if (n < NCLS) out[(long long)b * NCLS + n] = lg[j] * inv;
    }
}

// ---------------- host launch ----------------
extern "C" void kernel_launch(void* const* d_in, const int* in_sizes, int n_in,
                              void* d_out, int out_size) {
    const float* x      = (const float*)d_in[0];
    const float* conv_w = (const float*)d_in[1];
    const float* conv_b = (const float*)d_in[2];
    const float* pos    = (const float*)d_in[3];
    const float* cls    = (const float*)d_in[4];
    const float* ln1_s  = (const float*)d_in[5];
    const float* ln1_b  = (const float*)d_in[6];
    const float* ln2_s  = (const float*)d_in[7];
    const float* ln2_b  = (const float*)d_in[8];
    const float* w1     = (const float*)d_in[9];
    const float* b1     = (const float*)d_in[10];
    const float* w2     = (const float*)d_in[11];
    const float* b2     = (const float*)d_in[12];
    const float* hls    = (const float*)d_in[13];
    const float* hlb    = (const float*)d_in[14];
    const float* hw     = (const float*)d_in[15];
    const float* hb     = (const float*)d_in[16];
    float* out = (float*)d_out;

    float *t, *h, *hid;
    cudaGetSymbolAddress((void**)&t,   g_t);
    cudaGetSymbolAddress((void**)&h,   g_h);
    cudaGetSymbolAddress((void**)&hid, g_hid);

    fill_dft_d<<<256, 256>>>();
    fill_dft_n<<<NT, 256>>>();
    transpose_w<<<768, 256>>>(conv_w);
    patch_embed<<<dim3(128, 64), 256>>>(x);
    assemble<<<dim3(NT, 64), 256>>>(conv_b, pos, cls);

    const int MROWS = 64 * NT;  // 65600 = 64*1025, divisible by 64
    for (int i = 0; i < 6; i++) {
        ln_kernel<<<MROWS, 256>>>(t, h, ln1_s + (size_t)i * ND, ln1_b + (size_t)i * ND);
        dft_gemm<<<dim3(4, 1025), 256>>>();
        mix_gemm<<<dim3(4, 17, 64), 256>>>();
        ln_kernel<<<MROWS, 256>>>(t, h, ln2_s + (size_t)i * ND, ln2_b + (size_t)i * ND);
        sgemm_kernel<0, 1, 1><<<dim3(16, 1025), 256>>>(
            h, w1 + (size_t)i * ND * NH, hid, b1 + (size_t)i * NH, MROWS, NH, ND);
        sgemm_kernel<1, 1, 0><<<dim3(4, 1025), 256>>>(
            hid, w2 + (size_t)i * NH * ND, t, b2 + (size_t)i * ND, MROWS, ND, NH);
    }

    pool_kernel<<<64, 256>>>();
    head_kernel<<<64, 256>>>(hw, hb, hls, hlb, out);
}